// round 15
// baseline (speedup 1.0000x reference)
#include <cuda_runtime.h>

#define BB 1024
#define LL 4096
#define DD 64
#define KK 64
#define NCHUNK 2
#define CROWS (LL / NCHUNK)       // 2048 rows per chunk
#define NTHREADS 256
#define NWARPS 8
#define WR (CROWS / NWARPS)       // 256 rows per warp
#define NTILES (WR / 8)           // 32 tiles of 8 rows

typedef unsigned long long u64;

__device__ int g_mask_mode;                 // 0=int32, 1=byte, 2=float32
__device__ u64 g_part[BB * NCHUNK * KK];    // 1 MB chunk-top64 scratch
__device__ int g_count[BB];                 // per-batch arrival counters (self-resetting)

// ---------------------------------------------------------------------------
__global__ void detect_mask_kernel(const unsigned int* __restrict__ m) {
    __shared__ int f_byte, f_float;
    int tid = threadIdx.x;
    if (tid == 0) { f_byte = 0; f_float = 0; }
    __syncthreads();
    unsigned int w = m[tid];
    if (w == 0x3F800000u) f_float = 1;
    else if (w > 1u)      f_byte = 1;
    __syncthreads();
    if (tid == 0) g_mask_mode = f_float ? 2 : (f_byte ? 1 : 0);
}

__device__ __forceinline__ void cp_async16(unsigned int saddr, const void* g) {
    asm volatile("cp.async.cg.shared.global [%0], [%1], 16;" :: "r"(saddr), "l"(g));
}

// compare-exchange: after call, (a,b) ordered desc if d else asc
__device__ __forceinline__ void ce(u64& a, u64& b, bool d) {
    if ((a < b) == d) { u64 t = a; a = b; b = t; }
}

// ---------------------------------------------------------------------------
// Kernel A (fused): one CTA per (batch, half). Each warp streams 256 rows as
// two 128-row halves; keys captured straight into sort registers; register
// bitonic top-64 per half; register merge of halves; CTA merge -> g_part;
// last-arriving chunk-CTA merges the batch, gathers rows, writes mask.
// ---------------------------------------------------------------------------
__global__ __launch_bounds__(NTHREADS, 5) void gsu_score_kernel(
    const float* __restrict__ tgt,
    const float* __restrict__ seq,
    const void*  __restrict__ mraw,
    const float* __restrict__ W,
    float* __restrict__ out_emb,
    float* __restrict__ out_mask,
    int write_mask)
{
    __shared__ u64 keys[NWARPS * KK];                   // 4 KB (sorted lists / merge scratch)
    __shared__ float4 tiles[NWARPS * 2 * 128];          // 32 KB (reused as merge buf)
    __shared__ float ts[DD];
    __shared__ float qs[DD];
    __shared__ int s_last;

    const int b   = blockIdx.x >> 1;
    const int c   = blockIdx.x & 1;
    const int tid = threadIdx.x;
    const int lane = tid & 31;
    const int warp = tid >> 5;

    // --- mask -> ballot words, one register per 128-row half ---
    // Lane l loads rows h*128 + 4l..4l+3; ballot wj bit l = valid(4l+j).
    // Consumer of local row rho reads word rho&3 (== lane&3), bit rho>>2.
    unsigned int mk0, mk1;
    {
        const int mode = g_mask_mode;
        const size_t base = (size_t)b * LL + (size_t)c * CROWS + warp * WR;
#pragma unroll
        for (int h = 0; h < 2; h++) {
            const size_t mi = base + h * 128 + lane * 4;
            bool b0, b1, b2, b3;
            if (mode == 1) {
                uchar4 v = *(const uchar4*)((const unsigned char*)mraw + mi);
                b0 = v.x != 0; b1 = v.y != 0; b2 = v.z != 0; b3 = v.w != 0;
            } else if (mode == 2) {
                float4 v = *(const float4*)((const float*)mraw + mi);
                b0 = v.x != 0.0f; b1 = v.y != 0.0f; b2 = v.z != 0.0f; b3 = v.w != 0.0f;
            } else {
                int4 v = *(const int4*)((const int*)mraw + mi);
                b0 = v.x != 0; b1 = v.y != 0; b2 = v.z != 0; b3 = v.w != 0;
            }
            unsigned int w0 = __ballot_sync(0xFFFFFFFFu, b0);
            unsigned int w1 = __ballot_sync(0xFFFFFFFFu, b1);
            unsigned int w2 = __ballot_sync(0xFFFFFFFFu, b2);
            unsigned int w3 = __ballot_sync(0xFFFFFFFFu, b3);
            const int j = lane & 3;
            unsigned int sel = (j == 0) ? w0 : (j == 1) ? w1 : (j == 2) ? w2 : w3;
            if (h == 0) mk0 = sel; else mk1 = sel;
        }
    }

    if (tid < DD) ts[tid] = tgt[b * DD + tid];
    __syncthreads();
    if (tid < DD) {
        const float* wr = W + tid * DD;
        float acc = 0.0f;
#pragma unroll
        for (int j = 0; j < DD; j++) acc = fmaf(wr[j], ts[j], acc);
        qs[tid] = acc * 0.125f;     // exact 1/sqrt(64)
    }
    __syncthreads();

    // --- streaming constants (R12-proven layout) ---
    const int r     = lane & 7;
    const int piece = lane >> 3;
    float4 qr[4];
#pragma unroll
    for (int j = 0; j < 4; j++) qr[j] = ((const float4*)qs)[piece * 4 + j];

    const float4* seq4 = (const float4*)(seq + ((size_t)b * LL + (size_t)c * CROWS) * DD);
    float4* twarp = tiles + warp * 256;
    const unsigned int tbase = (unsigned int)__cvta_generic_to_shared(twarp);

    unsigned int dstoff[4];
#pragma unroll
    for (int it = 0; it < 4; it++) {
        const int idx  = it * 32 + lane;
        const int trow = idx >> 4, tcol = idx & 15;
        dstoff[it] = tbase + (unsigned)((trow * 16 + (tcol ^ trow)) << 4);
    }
    const int i0 = (piece * 4 + 0) ^ r;
    const int i1 = (piece * 4 + 1) ^ r;
    const int i2 = (piece * 4 + 2) ^ r;
    const int i3 = (piece * 4 + 3) ^ r;
    const float4* tb0 = twarp + r * 16;
    const float4* tb1 = twarp + 128 + r * 16;
    const float4* src = seq4 + (size_t)(warp * WR) * 16 + lane;
    const unsigned int shbase = (unsigned)(r >> 2);
    const int gsel = lane >> 3;     // which tile-group this lane captures

    // --- register sort helpers (4 keys/lane) ---
    u64 a[4];
    auto xstep4 = [&](int lmask, bool d) {
        const bool keepmax = (d == ((lane & lmask) == 0));
        u64 o0 = __shfl_xor_sync(0xFFFFFFFFu, a[0], lmask);
        u64 o1 = __shfl_xor_sync(0xFFFFFFFFu, a[1], lmask);
        u64 o2 = __shfl_xor_sync(0xFFFFFFFFu, a[2], lmask);
        u64 o3 = __shfl_xor_sync(0xFFFFFFFFu, a[3], lmask);
        if (keepmax) { a[0] = a[0] > o0 ? a[0] : o0; a[1] = a[1] > o1 ? a[1] : o1;
                       a[2] = a[2] > o2 ? a[2] : o2; a[3] = a[3] > o3 ? a[3] : o3; }
        else         { a[0] = a[0] < o0 ? a[0] : o0; a[1] = a[1] < o1 ? a[1] : o1;
                       a[2] = a[2] < o2 ? a[2] : o2; a[3] = a[3] < o3 ? a[3] : o3; }
    };
    auto intra4 = [&](bool d) {
        ce(a[0], a[2], d); ce(a[1], a[3], d);
        ce(a[0], a[1], d); ce(a[2], a[3], d);
    };
    // desc merge of a bitonic 64-seq laid out 4/lane on lanes<16
    auto merge64 = [&]() {
#pragma unroll
        for (int m = 8; m >= 1; m >>= 1) {
            const bool keepmax = ((lane & m) == 0);
            u64 o0 = __shfl_xor_sync(0xFFFFFFFFu, a[0], m);
            u64 o1 = __shfl_xor_sync(0xFFFFFFFFu, a[1], m);
            u64 o2 = __shfl_xor_sync(0xFFFFFFFFu, a[2], m);
            u64 o3 = __shfl_xor_sync(0xFFFFFFFFu, a[3], m);
            if (keepmax) { a[0] = a[0] > o0 ? a[0] : o0; a[1] = a[1] > o1 ? a[1] : o1;
                           a[2] = a[2] > o2 ? a[2] : o2; a[3] = a[3] > o3 ? a[3] : o3; }
            else         { a[0] = a[0] < o0 ? a[0] : o0; a[1] = a[1] < o1 ? a[1] : o1;
                           a[2] = a[2] < o2 ? a[2] : o2; a[3] = a[3] < o3 ? a[3] : o3; }
        }
        ce(a[0], a[2], true); ce(a[1], a[3], true);
        ce(a[0], a[1], true); ce(a[2], a[3], true);
    };

    u64 A[4];                        // half-0 sorted top-64 (4/lane, lanes<16)

    // prime pipeline: tile 0 into buf0
    {
#pragma unroll
        for (int it = 0; it < 4; it++)
            cp_async16(dstoff[it], src + it * 32);
        asm volatile("cp.async.commit_group;");
    }

#pragma unroll 1
    for (int h = 0; h < 2; h++) {
        const unsigned int mh = h ? mk1 : mk0;
#pragma unroll 1
        for (int g = 0; g < 4; g++) {
#pragma unroll
            for (int j = 0; j < 4; j++) {
                const int t = h * 16 + g * 4 + j;
                if (t + 1 < NTILES) {
                    const unsigned int bufo = ((t + 1) & 1) ? 2048u : 0u;
                    const float4* s2 = src + (t + 1) * 128;
#pragma unroll
                    for (int it = 0; it < 4; it++)
                        cp_async16(dstoff[it] + bufo, s2 + it * 32);
                    asm volatile("cp.async.commit_group;");
                    asm volatile("cp.async.wait_group 1;");
                } else {
                    asm volatile("cp.async.wait_group 0;");
                }
                __syncwarp();

                const float4* tb = (t & 1) ? tb1 : tb0;
                float4 v0 = tb[i0], v1 = tb[i1], v2 = tb[i2], v3 = tb[i3];
                float s = v0.x * qr[0].x;
                s = fmaf(v0.y, qr[0].y, s); s = fmaf(v0.z, qr[0].z, s); s = fmaf(v0.w, qr[0].w, s);
                s = fmaf(v1.x, qr[1].x, s); s = fmaf(v1.y, qr[1].y, s);
                s = fmaf(v1.z, qr[1].z, s); s = fmaf(v1.w, qr[1].w, s);
                s = fmaf(v2.x, qr[2].x, s); s = fmaf(v2.y, qr[2].y, s);
                s = fmaf(v2.z, qr[2].z, s); s = fmaf(v2.w, qr[2].w, s);
                s = fmaf(v3.x, qr[3].x, s); s = fmaf(v3.y, qr[3].y, s);
                s = fmaf(v3.z, qr[3].z, s); s = fmaf(v3.w, qr[3].w, s);
                s += __shfl_xor_sync(0xFFFFFFFFu, s, 8);
                s += __shfl_xor_sync(0xFFFFFFFFu, s, 16);
                __syncwarp();

                // every lane has score of local row (g*4+j)*8 + r; capture own
                const bool valid = (mh >> (8 * g + 2 * j + shbase)) & 1u;
                float sv = valid ? s : -1e9f;
                unsigned int fu = __float_as_uint(sv);
                fu = (fu & 0x80000000u) ? ~fu : (fu | 0x80000000u);
                const int grow = c * CROWS + warp * WR + h * 128 + (g * 4 + j) * 8 + r;
                u64 key = ((u64)fu << 32) | (u64)(0xFFFFFFFFu ^ (unsigned)grow);
                if (gsel == g) a[j] = key;
            }
        }

        // --- register bitonic: sort 128 captured keys, keep top-64 desc ---
        ce(a[0], a[1], true); ce(a[2], a[3], false);                       // k=2
        { const bool d = ((lane & 1) == 0);  intra4(d); }                  // k=4
        { const bool d = ((lane & 2) == 0);  xstep4(1, d); intra4(d); }    // k=8
        { const bool d = ((lane & 4) == 0);  xstep4(2, d); xstep4(1, d); intra4(d); }             // k=16
        { const bool d = ((lane & 8) == 0);  xstep4(4, d); xstep4(2, d); xstep4(1, d); intra4(d); } // k=32
        { const bool d = ((lane & 16) == 0); xstep4(8, d); xstep4(4, d); xstep4(2, d); xstep4(1, d); intra4(d); } // k=64
        {   // compact 128 -> 64 (positions 0-63 valid in lanes<16, bitonic)
            u64 o0 = __shfl_xor_sync(0xFFFFFFFFu, a[0], 16);
            u64 o1 = __shfl_xor_sync(0xFFFFFFFFu, a[1], 16);
            u64 o2 = __shfl_xor_sync(0xFFFFFFFFu, a[2], 16);
            u64 o3 = __shfl_xor_sync(0xFFFFFFFFu, a[3], 16);
            a[0] = a[0] > o0 ? a[0] : o0; a[1] = a[1] > o1 ? a[1] : o1;
            a[2] = a[2] > o2 ? a[2] : o2; a[3] = a[3] > o3 ? a[3] : o3;
        }
        merge64();                    // sorted desc, 4/lane, lanes<16

        if (h == 0) {
            A[0] = a[0]; A[1] = a[1]; A[2] = a[2]; A[3] = a[3];
        } else {
            // merge halves: reverse B (pos 63-p -> lane l^15, slot 3-j), max, merge
            u64 r0 = __shfl_xor_sync(0xFFFFFFFFu, a[3], 15);
            u64 r1 = __shfl_xor_sync(0xFFFFFFFFu, a[2], 15);
            u64 r2 = __shfl_xor_sync(0xFFFFFFFFu, a[1], 15);
            u64 r3 = __shfl_xor_sync(0xFFFFFFFFu, a[0], 15);
            a[0] = A[0] > r0 ? A[0] : r0;
            a[1] = A[1] > r1 ? A[1] : r1;
            a[2] = A[2] > r2 ? A[2] : r2;
            a[3] = A[3] > r3 ? A[3] : r3;
            merge64();                // exact top-64 of 256, desc
        }
    }

    // store warp's sorted top-64 (lanes<16, positions 4l+j)
    if (lane < 16) {
        ulonglong2 p0; p0.x = a[0]; p0.y = a[1];
        ulonglong2 p1; p1.x = a[2]; p1.y = a[3];
        ((ulonglong2*)(keys + warp * KK))[2 * lane]     = p0;
        ((ulonglong2*)(keys + warp * KK))[2 * lane + 1] = p1;
    }
    __syncthreads();

    // --- CTA merge: 8 desc lists (512 keys) -> 64, in tile buffer ---
    u64* mk = (u64*)tiles;
#pragma unroll
    for (int u = 0; u < 2; u++) {
        const int t = tid + u * NTHREADS;
        const int w = t >> 6, i = t & 63;
        const int srci = (w & 1) ? (63 - i) : i;
        mk[t] = keys[w * KK + srci];
    }
    __syncthreads();
    for (int live = 256; live >= 64; live >>= 1) {
        u64 kp = 0;
        const bool act = tid < live;
        if (act) {
            const int p = tid >> 6, i = tid & 63;
            u64 aa = mk[p * 128 + i];
            u64 cc = mk[p * 128 + 64 + i];
            kp = (aa > cc) ? aa : cc;
        }
        __syncthreads();
        if (act) mk[tid] = kp;
        __syncthreads();
        for (int j = 32; j > 0; j >>= 1) {
            if (tid < live / 2) {
                const int i   = ((tid & ~(j - 1)) << 1) | (tid & (j - 1));
                const int ixj = i | j;
                u64 aa = mk[i], cc = mk[ixj];
                bool cdesc = (((i >> 6) & 1) == 0);
                if ((aa < cc) == cdesc) { mk[i] = cc; mk[ixj] = aa; }
            }
            __syncthreads();
        }
    }

    if (tid < KK) g_part[(size_t)blockIdx.x * KK + tid] = mk[tid];
    __syncthreads();

    // --- fused batch merge: last-arriving chunk-CTA finishes the batch ---
    if (tid == 0) {
        __threadfence();
        s_last = (atomicAdd(&g_count[b], 1) == NCHUNK - 1);
    }
    __syncthreads();
    if (!s_last) return;
    __threadfence();

    u64* sk = keys;                                      // 128 keys scratch
    if (tid < NCHUNK * KK) {
        const int cidx = tid >> 6, i = tid & 63;
        const int srci = (cidx & 1) ? (63 - i) : i;
        sk[tid] = g_part[((size_t)b * NCHUNK + cidx) * KK + srci];
    }
    __syncthreads();

    for (int live = 64; live >= 64; live >>= 1) {
        u64 kp = 0;
        const bool act = tid < live;
        if (act) {
            u64 aa = sk[tid];
            u64 cc = sk[tid + 64];
            kp = (aa > cc) ? aa : cc;
        }
        __syncthreads();
        if (act) sk[tid] = kp;
        __syncthreads();
        for (int j = 32; j > 0; j >>= 1) {
            if (tid < live / 2) {
                const int i   = ((tid & ~(j - 1)) << 1) | (tid & (j - 1));
                const int ixj = i | j;
                u64 aa = sk[i], cc = sk[ixj];
                if (aa < cc) { sk[i] = cc; sk[ixj] = aa; }
            }
            __syncthreads();
        }
    }
    // sk[0..63] = exact global top-64, descending, jax tie-break.

    const float4* seqb4 = (const float4*)(seq + (size_t)b * LL * DD);
    float4* out4 = (float4*)(out_emb + (size_t)b * KK * DD);
#pragma unroll
    for (int u = 0; u < KK * DD / 4 / NTHREADS; u++) {
        const int i   = tid + u * NTHREADS;
        const int kk  = i >> 4;
        const int off = i & 15;
        const int idx = (int)(0xFFFFFFFFu ^ (unsigned int)sk[kk]);
        out4[i] = seqb4[(size_t)idx * (DD / 4) + off];
    }

    if (write_mask && tid < KK) {
        unsigned int fu = (unsigned int)(sk[tid] >> 32);
        unsigned int bits = (fu & 0x80000000u) ? (fu ^ 0x80000000u) : ~fu;
        float s = __uint_as_float(bits);
        out_mask[(size_t)b * KK + tid] = (s > -1e8f) ? 1.0f : 0.0f;
    }

    if (tid == 0) g_count[b] = 0;
}

// ---------------------------------------------------------------------------
extern "C" void kernel_launch(void* const* d_in, const int* in_sizes, int n_in,
                              void* d_out, int out_size)
{
    const float* tgt  = (const float*)d_in[0];
    const float* seq  = (const float*)d_in[2];
    const void*  mask = d_in[4];

    int w_idx = n_in - 1;
    for (int i = n_in - 1; i >= 0; i--) {
        if (in_sizes[i] == DD * DD) { w_idx = i; break; }
    }
    const float* W = (const float*)d_in[w_idx];

    float* out      = (float*)d_out;
    int write_mask  = (out_size >= BB * KK * DD + BB * KK) ? 1 : 0;
    float* out_mask = out + (size_t)BB * KK * DD;

    detect_mask_kernel<<<1, 1024>>>((const unsigned int*)mask);
    gsu_score_kernel<<<BB * NCHUNK, NTHREADS>>>(tgt, seq, mask, W, out, out_mask, write_mask);
}

// round 16
// speedup vs baseline: 1.0263x; 1.0263x over previous
#include <cuda_runtime.h>

#define BB 1024
#define LL 4096
#define DD 64
#define KK 64
#define NCHUNK 4
#define CROWS (LL / NCHUNK)       // 1024 rows per chunk
#define NTHREADS 256
#define NWARPS 8
#define WR (CROWS / NWARPS)       // 128 rows per warp
#define NTILES (WR / 8)           // 16 tiles of 8 rows

typedef unsigned long long u64;

__device__ int g_mask_mode;                 // 0=int32, 1=byte, 2=float32
__device__ u64 g_part[BB * NCHUNK * KK];    // 2 MB chunk-top64 scratch
__device__ int g_count[BB];                 // per-batch arrival counters (self-resetting)

// ---------------------------------------------------------------------------
__global__ void detect_mask_kernel(const unsigned int* __restrict__ m) {
    __shared__ int f_byte, f_float;
    int tid = threadIdx.x;
    if (tid == 0) { f_byte = 0; f_float = 0; }
    __syncthreads();
    unsigned int w = m[tid];
    if (w == 0x3F800000u) f_float = 1;
    else if (w > 1u)      f_byte = 1;
    __syncthreads();
    if (tid == 0) g_mask_mode = f_float ? 2 : (f_byte ? 1 : 0);
}

__device__ __forceinline__ void cp_async16(unsigned int saddr, const void* g) {
    asm volatile("cp.async.cg.shared.global [%0], [%1], 16;" :: "r"(saddr), "l"(g));
}

// compare-exchange: after call, (a,b) ordered desc if d else asc
__device__ __forceinline__ void ce(u64& a, u64& b, bool d) {
    if ((a < b) == d) { u64 t = a; a = b; b = t; }
}

// ---------------------------------------------------------------------------
// Kernel A (fused): one CTA per (batch, chunk) — R12 structure. Scores are
// captured DIRECTLY into sort registers (R15 mechanism, no smem key staging);
// register bitonic top-64; CTA merge -> g_part; last-arriving chunk-CTA
// merges the batch, gathers rows, writes mask.
// ---------------------------------------------------------------------------
__global__ __launch_bounds__(NTHREADS, 5) void gsu_score_kernel(
    const float* __restrict__ tgt,
    const float* __restrict__ seq,
    const void*  __restrict__ mraw,
    const float* __restrict__ W,
    float* __restrict__ out_emb,
    float* __restrict__ out_mask,
    int write_mask)
{
    __shared__ u64 keys[NWARPS * KK];                   // 4 KB (sorted lists / merge scratch)
    __shared__ float4 tiles[NWARPS * 2 * 128];          // 32 KB (reused as merge buf)
    __shared__ float ts[DD];
    __shared__ float qs[DD];
    __shared__ int s_last;

    const int b   = blockIdx.x >> 2;
    const int c   = blockIdx.x & 3;
    const int tid = threadIdx.x;
    const int lane = tid & 31;
    const int warp = tid >> 5;

    // --- mask -> ballot words -> per-thread mask register (R12-proven) ---
    // Lane l loads rows 4l..4l+3 of this warp's 128-row segment; ballot wj
    // bit l = validity of row 4l+j. Consumer of row t*8+r reads word r&3
    // (== lane&3 for its own row), bit 2t + (r>>2).
    unsigned int mymask;
    {
        const int mode = g_mask_mode;
        const size_t mi = (size_t)b * LL + (size_t)c * CROWS + warp * WR + lane * 4;
        bool b0, b1, b2, b3;
        if (mode == 1) {
            uchar4 v = *(const uchar4*)((const unsigned char*)mraw + mi);
            b0 = v.x != 0; b1 = v.y != 0; b2 = v.z != 0; b3 = v.w != 0;
        } else if (mode == 2) {
            float4 v = *(const float4*)((const float*)mraw + mi);
            b0 = v.x != 0.0f; b1 = v.y != 0.0f; b2 = v.z != 0.0f; b3 = v.w != 0.0f;
        } else {
            int4 v = *(const int4*)((const int*)mraw + mi);
            b0 = v.x != 0; b1 = v.y != 0; b2 = v.z != 0; b3 = v.w != 0;
        }
        unsigned int w0 = __ballot_sync(0xFFFFFFFFu, b0);
        unsigned int w1 = __ballot_sync(0xFFFFFFFFu, b1);
        unsigned int w2 = __ballot_sync(0xFFFFFFFFu, b2);
        unsigned int w3 = __ballot_sync(0xFFFFFFFFu, b3);
        const int j = lane & 3;
        mymask = (j == 0) ? w0 : (j == 1) ? w1 : (j == 2) ? w2 : w3;
    }

    if (tid < DD) ts[tid] = tgt[b * DD + tid];
    __syncthreads();
    if (tid < DD) {
        const float* wr = W + tid * DD;
        float acc = 0.0f;
#pragma unroll
        for (int j = 0; j < DD; j++) acc = fmaf(wr[j], ts[j], acc);
        qs[tid] = acc * 0.125f;     // exact 1/sqrt(64)
    }
    __syncthreads();

    // --- streaming constants (proven layout) ---
    const int r     = lane & 7;
    const int piece = lane >> 3;
    float4 qr[4];
#pragma unroll
    for (int j = 0; j < 4; j++) qr[j] = ((const float4*)qs)[piece * 4 + j];

    const float4* seq4 = (const float4*)(seq + ((size_t)b * LL + (size_t)c * CROWS) * DD);
    float4* twarp = tiles + warp * 256;
    const unsigned int tbase = (unsigned int)__cvta_generic_to_shared(twarp);

    unsigned int dstoff[4];
#pragma unroll
    for (int it = 0; it < 4; it++) {
        const int idx  = it * 32 + lane;
        const int trow = idx >> 4, tcol = idx & 15;
        dstoff[it] = tbase + (unsigned)((trow * 16 + (tcol ^ trow)) << 4);
    }
    const int i0 = (piece * 4 + 0) ^ r;
    const int i1 = (piece * 4 + 1) ^ r;
    const int i2 = (piece * 4 + 2) ^ r;
    const int i3 = (piece * 4 + 3) ^ r;
    const float4* tb0 = twarp + r * 16;
    const float4* tb1 = twarp + 128 + r * 16;
    const float4* src = seq4 + (size_t)(warp * WR) * 16 + lane;
    const unsigned int shbase = (unsigned)(r >> 2);
    const int gsel = lane >> 3;     // which tile-group this lane captures

    // --- register sort state + helpers (R15-proven) ---
    u64 a[4];
    auto xstep4 = [&](int lmask, bool d) {
        const bool keepmax = (d == ((lane & lmask) == 0));
        u64 o0 = __shfl_xor_sync(0xFFFFFFFFu, a[0], lmask);
        u64 o1 = __shfl_xor_sync(0xFFFFFFFFu, a[1], lmask);
        u64 o2 = __shfl_xor_sync(0xFFFFFFFFu, a[2], lmask);
        u64 o3 = __shfl_xor_sync(0xFFFFFFFFu, a[3], lmask);
        if (keepmax) { a[0] = a[0] > o0 ? a[0] : o0; a[1] = a[1] > o1 ? a[1] : o1;
                       a[2] = a[2] > o2 ? a[2] : o2; a[3] = a[3] > o3 ? a[3] : o3; }
        else         { a[0] = a[0] < o0 ? a[0] : o0; a[1] = a[1] < o1 ? a[1] : o1;
                       a[2] = a[2] < o2 ? a[2] : o2; a[3] = a[3] < o3 ? a[3] : o3; }
    };
    auto intra4 = [&](bool d) {
        ce(a[0], a[2], d); ce(a[1], a[3], d);
        ce(a[0], a[1], d); ce(a[2], a[3], d);
    };
    auto merge64 = [&]() {           // desc merge of bitonic 64 (4/lane, lanes<16)
#pragma unroll
        for (int m = 8; m >= 1; m >>= 1) {
            const bool keepmax = ((lane & m) == 0);
            u64 o0 = __shfl_xor_sync(0xFFFFFFFFu, a[0], m);
            u64 o1 = __shfl_xor_sync(0xFFFFFFFFu, a[1], m);
            u64 o2 = __shfl_xor_sync(0xFFFFFFFFu, a[2], m);
            u64 o3 = __shfl_xor_sync(0xFFFFFFFFu, a[3], m);
            if (keepmax) { a[0] = a[0] > o0 ? a[0] : o0; a[1] = a[1] > o1 ? a[1] : o1;
                           a[2] = a[2] > o2 ? a[2] : o2; a[3] = a[3] > o3 ? a[3] : o3; }
            else         { a[0] = a[0] < o0 ? a[0] : o0; a[1] = a[1] < o1 ? a[1] : o1;
                           a[2] = a[2] < o2 ? a[2] : o2; a[3] = a[3] < o3 ? a[3] : o3; }
        }
        ce(a[0], a[2], true); ce(a[1], a[3], true);
        ce(a[0], a[1], true); ce(a[2], a[3], true);
    };

    // prime pipeline: tile 0 into buf0
    {
#pragma unroll
        for (int it = 0; it < 4; it++)
            cp_async16(dstoff[it], src + it * 32);
        asm volatile("cp.async.commit_group;");
    }

    // --- stream loop: wait(t), compute(t), capture into registers ---
#pragma unroll 1
    for (int g = 0; g < 4; g++) {
#pragma unroll
        for (int j = 0; j < 4; j++) {
            const int t = g * 4 + j;
            if (t + 1 < NTILES) {
                const unsigned int bufo = ((t + 1) & 1) ? 2048u : 0u;
                const float4* s2 = src + (t + 1) * 128;
#pragma unroll
                for (int it = 0; it < 4; it++)
                    cp_async16(dstoff[it] + bufo, s2 + it * 32);
                asm volatile("cp.async.commit_group;");
                asm volatile("cp.async.wait_group 1;");
            } else {
                asm volatile("cp.async.wait_group 0;");
            }
            __syncwarp();

            const float4* tb = (t & 1) ? tb1 : tb0;
            float4 v0 = tb[i0], v1 = tb[i1], v2 = tb[i2], v3 = tb[i3];
            float s = v0.x * qr[0].x;
            s = fmaf(v0.y, qr[0].y, s); s = fmaf(v0.z, qr[0].z, s); s = fmaf(v0.w, qr[0].w, s);
            s = fmaf(v1.x, qr[1].x, s); s = fmaf(v1.y, qr[1].y, s);
            s = fmaf(v1.z, qr[1].z, s); s = fmaf(v1.w, qr[1].w, s);
            s = fmaf(v2.x, qr[2].x, s); s = fmaf(v2.y, qr[2].y, s);
            s = fmaf(v2.z, qr[2].z, s); s = fmaf(v2.w, qr[2].w, s);
            s = fmaf(v3.x, qr[3].x, s); s = fmaf(v3.y, qr[3].y, s);
            s = fmaf(v3.z, qr[3].z, s); s = fmaf(v3.w, qr[3].w, s);
            s += __shfl_xor_sync(0xFFFFFFFFu, s, 8);
            s += __shfl_xor_sync(0xFFFFFFFFu, s, 16);
            __syncwarp();

            // every lane now holds score of local row t*8 + r; capture own key
            const bool valid = (mymask >> (2 * t + shbase)) & 1u;
            float sv = valid ? s : -1e9f;
            unsigned int fu = __float_as_uint(sv);
            fu = (fu & 0x80000000u) ? ~fu : (fu | 0x80000000u);
            const int grow = c * CROWS + warp * WR + t * 8 + r;
            u64 key = ((u64)fu << 32) | (u64)(0xFFFFFFFFu ^ (unsigned)grow);
            if (gsel == g) a[j] = key;
        }
    }

    // --- register bitonic: sort 128 keys, keep exact top-64 desc ---
    ce(a[0], a[1], true); ce(a[2], a[3], false);                       // k=2
    { const bool d = ((lane & 1) == 0);  intra4(d); }                  // k=4
    { const bool d = ((lane & 2) == 0);  xstep4(1, d); intra4(d); }    // k=8
    { const bool d = ((lane & 4) == 0);  xstep4(2, d); xstep4(1, d); intra4(d); }             // k=16
    { const bool d = ((lane & 8) == 0);  xstep4(4, d); xstep4(2, d); xstep4(1, d); intra4(d); } // k=32
    { const bool d = ((lane & 16) == 0); xstep4(8, d); xstep4(4, d); xstep4(2, d); xstep4(1, d); intra4(d); } // k=64
    {   // compact 128 -> 64 (positions 0-63 valid in lanes<16, bitonic)
        u64 o0 = __shfl_xor_sync(0xFFFFFFFFu, a[0], 16);
        u64 o1 = __shfl_xor_sync(0xFFFFFFFFu, a[1], 16);
        u64 o2 = __shfl_xor_sync(0xFFFFFFFFu, a[2], 16);
        u64 o3 = __shfl_xor_sync(0xFFFFFFFFu, a[3], 16);
        a[0] = a[0] > o0 ? a[0] : o0; a[1] = a[1] > o1 ? a[1] : o1;
        a[2] = a[2] > o2 ? a[2] : o2; a[3] = a[3] > o3 ? a[3] : o3;
    }
    merge64();                       // sorted desc, 4/lane, lanes<16

    // store warp's sorted top-64 (lanes<16, positions 4l+j)
    if (lane < 16) {
        ulonglong2 p0; p0.x = a[0]; p0.y = a[1];
        ulonglong2 p1; p1.x = a[2]; p1.y = a[3];
        ((ulonglong2*)(keys + warp * KK))[2 * lane]     = p0;
        ((ulonglong2*)(keys + warp * KK))[2 * lane + 1] = p1;
    }
    __syncthreads();

    // --- CTA merge: 8 desc lists (512 keys) -> 64, in tile buffer ---
    u64* mk = (u64*)tiles;
#pragma unroll
    for (int u = 0; u < 2; u++) {
        const int t = tid + u * NTHREADS;
        const int w = t >> 6, i = t & 63;
        const int srci = (w & 1) ? (63 - i) : i;
        mk[t] = keys[w * KK + srci];
    }
    __syncthreads();
    for (int live = 256; live >= 64; live >>= 1) {
        u64 kp = 0;
        const bool act = tid < live;
        if (act) {
            const int p = tid >> 6, i = tid & 63;
            u64 aa = mk[p * 128 + i];
            u64 cc = mk[p * 128 + 64 + i];
            kp = (aa > cc) ? aa : cc;
        }
        __syncthreads();
        if (act) mk[tid] = kp;
        __syncthreads();
        for (int j = 32; j > 0; j >>= 1) {
            if (tid < live / 2) {
                const int i   = ((tid & ~(j - 1)) << 1) | (tid & (j - 1));
                const int ixj = i | j;
                u64 aa = mk[i], cc = mk[ixj];
                bool cdesc = (((i >> 6) & 1) == 0);
                if ((aa < cc) == cdesc) { mk[i] = cc; mk[ixj] = aa; }
            }
            __syncthreads();
        }
    }

    if (tid < KK) g_part[(size_t)blockIdx.x * KK + tid] = mk[tid];
    __syncthreads();

    // --- fused batch merge: last-arriving chunk-CTA finishes the batch ---
    if (tid == 0) {
        __threadfence();
        s_last = (atomicAdd(&g_count[b], 1) == NCHUNK - 1);
    }
    __syncthreads();
    if (!s_last) return;
    __threadfence();

    u64* sk = (u64*)tiles;                               // 256 keys scratch
    if (tid < NCHUNK * KK) {
        const int cidx = tid >> 6, i = tid & 63;
        const int srci = (cidx & 1) ? (63 - i) : i;
        sk[tid] = g_part[((size_t)b * NCHUNK + cidx) * KK + srci];
    }
    __syncthreads();

    for (int live = 128; live >= 64; live >>= 1) {
        u64 kp = 0;
        const bool act = tid < live;
        if (act) {
            const int p = tid >> 6, i = tid & 63;
            u64 aa = sk[p * 128 + i];
            u64 cc = sk[p * 128 + 64 + i];
            kp = (aa > cc) ? aa : cc;
        }
        __syncthreads();
        if (act) sk[tid] = kp;
        __syncthreads();
        for (int j = 32; j > 0; j >>= 1) {
            if (tid < live / 2) {
                const int i   = ((tid & ~(j - 1)) << 1) | (tid & (j - 1));
                const int ixj = i | j;
                u64 aa = sk[i], cc = sk[ixj];
                bool cdesc = (((i >> 6) & 1) == 0);
                if ((aa < cc) == cdesc) { sk[i] = cc; sk[ixj] = aa; }
            }
            __syncthreads();
        }
    }
    // sk[0..63] = exact global top-64, descending, jax tie-break.

    const float4* seqb4 = (const float4*)(seq + (size_t)b * LL * DD);
    float4* out4 = (float4*)(out_emb + (size_t)b * KK * DD);
#pragma unroll
    for (int u = 0; u < KK * DD / 4 / NTHREADS; u++) {
        const int i   = tid + u * NTHREADS;
        const int kk  = i >> 4;
        const int off = i & 15;
        const int idx = (int)(0xFFFFFFFFu ^ (unsigned int)sk[kk]);
        out4[i] = seqb4[(size_t)idx * (DD / 4) + off];
    }

    if (write_mask && tid < KK) {
        unsigned int fu = (unsigned int)(sk[tid] >> 32);
        unsigned int bits = (fu & 0x80000000u) ? (fu ^ 0x80000000u) : ~fu;
        float s = __uint_as_float(bits);
        out_mask[(size_t)b * KK + tid] = (s > -1e8f) ? 1.0f : 0.0f;
    }

    if (tid == 0) g_count[b] = 0;
}

// ---------------------------------------------------------------------------
extern "C" void kernel_launch(void* const* d_in, const int* in_sizes, int n_in,
                              void* d_out, int out_size)
{
    const float* tgt  = (const float*)d_in[0];
    const float* seq  = (const float*)d_in[2];
    const void*  mask = d_in[4];

    int w_idx = n_in - 1;
    for (int i = n_in - 1; i >= 0; i--) {
        if (in_sizes[i] == DD * DD) { w_idx = i; break; }
    }
    const float* W = (const float*)d_in[w_idx];

    float* out      = (float*)d_out;
    int write_mask  = (out_size >= BB * KK * DD + BB * KK) ? 1 : 0;
    float* out_mask = out + (size_t)BB * KK * DD;

    detect_mask_kernel<<<1, 1024>>>((const unsigned int*)mask);
    gsu_score_kernel<<<BB * NCHUNK, NTHREADS>>>(tgt, seq, mask, W, out, out_mask, write_mask);
}

// round 17
// speedup vs baseline: 1.0346x; 1.0081x over previous
#include <cuda_runtime.h>

#define BB 1024
#define LL 4096
#define DD 64
#define KK 64
#define NCHUNK 4
#define CROWS (LL / NCHUNK)       // 1024 rows per chunk
#define NTHREADS 256
#define NWARPS 8
#define WR (CROWS / NWARPS)       // 128 rows per warp
#define NTILES (WR / 8)           // 16 tiles of 8 rows

typedef unsigned long long u64;

__device__ int g_mask_mode;                 // 0=int32, 1=byte, 2=float32
__device__ u64 g_part[BB * NCHUNK * KK];    // 2 MB chunk-top64 scratch
__device__ int g_count[BB];                 // per-batch arrival counters (self-resetting)

// ---------------------------------------------------------------------------
__global__ void detect_mask_kernel(const unsigned int* __restrict__ m) {
    __shared__ int f_byte, f_float;
    int tid = threadIdx.x;
    if (tid == 0) { f_byte = 0; f_float = 0; }
    __syncthreads();
    unsigned int w = m[tid];
    if (w == 0x3F800000u) f_float = 1;
    else if (w > 1u)      f_byte = 1;
    __syncthreads();
    if (tid == 0) g_mask_mode = f_float ? 2 : (f_byte ? 1 : 0);
}

__device__ __forceinline__ void cp_async16(unsigned int saddr, const void* g) {
    asm volatile("cp.async.cg.shared.global [%0], [%1], 16;" :: "r"(saddr), "l"(g));
}

// compare-exchange: after call, (a,b) ordered desc if d else asc
__device__ __forceinline__ void ce(u64& a, u64& b, bool d) {
    if ((a < b) == d) { u64 t = a; a = b; b = t; }
}

// ---------------------------------------------------------------------------
// Kernel A (fused): one CTA per (batch, chunk) — R12 structure. Streaming +
// per-warp register top-64 sort exactly as the 207.6us kernel; the CTA merge
// and batch merge are replaced by warp-register merge trees (3+2 barriers
// instead of ~24+~12).
// ---------------------------------------------------------------------------
__global__ __launch_bounds__(NTHREADS, 5) void gsu_score_kernel(
    const float* __restrict__ tgt,
    const float* __restrict__ seq,
    const void*  __restrict__ mraw,
    const float* __restrict__ W,
    float* __restrict__ out_emb,
    float* __restrict__ out_mask,
    int write_mask)
{
    __shared__ __align__(16) u64 keys[CROWS];           // 8 KB (warp lists / final keys)
    __shared__ float4 tiles[NWARPS * 2 * 128];          // 32 KB (reused as merge buf)
    __shared__ float ts[DD];
    __shared__ float qs[DD];
    __shared__ int s_last;

    const int b   = blockIdx.x >> 2;
    const int c   = blockIdx.x & 3;
    const int tid = threadIdx.x;
    const int lane = tid & 31;
    const int warp = tid >> 5;

    // --- mask -> ballot words -> per-thread mask register (R12-proven) ---
    unsigned int mymask;
    {
        const int mode = g_mask_mode;
        const size_t mi = (size_t)b * LL + (size_t)c * CROWS + warp * WR + lane * 4;
        bool b0, b1, b2, b3;
        if (mode == 1) {
            uchar4 v = *(const uchar4*)((const unsigned char*)mraw + mi);
            b0 = v.x != 0; b1 = v.y != 0; b2 = v.z != 0; b3 = v.w != 0;
        } else if (mode == 2) {
            float4 v = *(const float4*)((const float*)mraw + mi);
            b0 = v.x != 0.0f; b1 = v.y != 0.0f; b2 = v.z != 0.0f; b3 = v.w != 0.0f;
        } else {
            int4 v = *(const int4*)((const int*)mraw + mi);
            b0 = v.x != 0; b1 = v.y != 0; b2 = v.z != 0; b3 = v.w != 0;
        }
        unsigned int w0 = __ballot_sync(0xFFFFFFFFu, b0);
        unsigned int w1 = __ballot_sync(0xFFFFFFFFu, b1);
        unsigned int w2 = __ballot_sync(0xFFFFFFFFu, b2);
        unsigned int w3 = __ballot_sync(0xFFFFFFFFu, b3);
        const int j = lane & 3;
        mymask = (j == 0) ? w0 : (j == 1) ? w1 : (j == 2) ? w2 : w3;
    }

    if (tid < DD) ts[tid] = tgt[b * DD + tid];
    __syncthreads();
    if (tid < DD) {
        const float* wr = W + tid * DD;
        float acc = 0.0f;
#pragma unroll
        for (int j = 0; j < DD; j++) acc = fmaf(wr[j], ts[j], acc);
        qs[tid] = acc * 0.125f;     // exact 1/sqrt(64)
    }
    __syncthreads();

    // --- scoring: per-warp double-buffered cp.async pipeline (proven) ---
    const int r     = lane & 7;
    const int piece = lane >> 3;
    float4 qr[4];
#pragma unroll
    for (int j = 0; j < 4; j++) qr[j] = ((const float4*)qs)[piece * 4 + j];

    const float4* seq4 = (const float4*)(seq + ((size_t)b * LL + (size_t)c * CROWS) * DD);
    float4* twarp = tiles + warp * 256;
    const unsigned int tbase = (unsigned int)__cvta_generic_to_shared(twarp);

    unsigned int dstoff[4];
#pragma unroll
    for (int it = 0; it < 4; it++) {
        const int idx  = it * 32 + lane;
        const int trow = idx >> 4, tcol = idx & 15;
        dstoff[it] = tbase + (unsigned)((trow * 16 + (tcol ^ trow)) << 4);
    }
    const int i0 = (piece * 4 + 0) ^ r;
    const int i1 = (piece * 4 + 1) ^ r;
    const int i2 = (piece * 4 + 2) ^ r;
    const int i3 = (piece * 4 + 3) ^ r;
    const float4* tb0 = twarp + r * 16;
    const float4* tb1 = twarp + 128 + r * 16;
    const float4* src = seq4 + (size_t)(warp * WR) * 16 + lane;
    const unsigned int shbase = (unsigned)(r >> 2);

    {
#pragma unroll
        for (int it = 0; it < 4; it++)
            cp_async16(dstoff[it], src + it * 32);
        asm volatile("cp.async.commit_group;");
    }
#pragma unroll 1
    for (int t = 0; t < NTILES; t++) {
        if (t + 1 < NTILES) {
            const unsigned int bufo = ((t + 1) & 1) ? 2048u : 0u;
            const float4* s2 = src + (t + 1) * 128;
#pragma unroll
            for (int it = 0; it < 4; it++)
                cp_async16(dstoff[it] + bufo, s2 + it * 32);
            asm volatile("cp.async.commit_group;");
            asm volatile("cp.async.wait_group 1;");
        } else {
            asm volatile("cp.async.wait_group 0;");
        }
        __syncwarp();

        const float4* tb = (t & 1) ? tb1 : tb0;
        float4 v0 = tb[i0], v1 = tb[i1], v2 = tb[i2], v3 = tb[i3];
        float s = v0.x * qr[0].x;
        s = fmaf(v0.y, qr[0].y, s); s = fmaf(v0.z, qr[0].z, s); s = fmaf(v0.w, qr[0].w, s);
        s = fmaf(v1.x, qr[1].x, s); s = fmaf(v1.y, qr[1].y, s);
        s = fmaf(v1.z, qr[1].z, s); s = fmaf(v1.w, qr[1].w, s);
        s = fmaf(v2.x, qr[2].x, s); s = fmaf(v2.y, qr[2].y, s);
        s = fmaf(v2.z, qr[2].z, s); s = fmaf(v2.w, qr[2].w, s);
        s = fmaf(v3.x, qr[3].x, s); s = fmaf(v3.y, qr[3].y, s);
        s = fmaf(v3.z, qr[3].z, s); s = fmaf(v3.w, qr[3].w, s);
        s += __shfl_xor_sync(0xFFFFFFFFu, s, 8);
        s += __shfl_xor_sync(0xFFFFFFFFu, s, 16);
        __syncwarp();

        if (lane < 8) {
            const int lrow = warp * WR + t * 8 + r;
            const int grow = c * CROWS + lrow;
            const bool valid = (mymask >> (2 * t + shbase)) & 1u;
            float sv = valid ? s : -1e9f;
            unsigned int fu = __float_as_uint(sv);
            fu = (fu & 0x80000000u) ? ~fu : (fu | 0x80000000u);
            keys[lrow] = ((u64)fu << 32) | (u64)(0xFFFFFFFFu ^ (unsigned)grow);
        }
    }
    __syncwarp();

    // --- REGISTER warp sort: exact top-64 of 128, sorted desc (R12-proven) ---
    u64* seg = keys + warp * WR;
    u64 a0, a1, a2, a3;     // positions 4l .. 4l+3
    {
        ulonglong2 p0 = ((const ulonglong2*)seg)[2 * lane];
        ulonglong2 p1 = ((const ulonglong2*)seg)[2 * lane + 1];
        a0 = p0.x; a1 = p0.y; a2 = p1.x; a3 = p1.y;
    }

    auto xstep = [&](int lmask, bool d) {
        const bool keepmax = (d == ((lane & lmask) == 0));
        u64 o0 = __shfl_xor_sync(0xFFFFFFFFu, a0, lmask);
        u64 o1 = __shfl_xor_sync(0xFFFFFFFFu, a1, lmask);
        u64 o2 = __shfl_xor_sync(0xFFFFFFFFu, a2, lmask);
        u64 o3 = __shfl_xor_sync(0xFFFFFFFFu, a3, lmask);
        if (keepmax) { a0 = a0 > o0 ? a0 : o0; a1 = a1 > o1 ? a1 : o1;
                       a2 = a2 > o2 ? a2 : o2; a3 = a3 > o3 ? a3 : o3; }
        else         { a0 = a0 < o0 ? a0 : o0; a1 = a1 < o1 ? a1 : o1;
                       a2 = a2 < o2 ? a2 : o2; a3 = a3 < o3 ? a3 : o3; }
    };
    auto intra = [&](bool d) {
        ce(a0, a2, d); ce(a1, a3, d);
        ce(a0, a1, d); ce(a2, a3, d);
    };

    ce(a0, a1, true); ce(a2, a3, false);                                   // k=2
    { const bool d = ((lane & 1) == 0);  intra(d); }                       // k=4
    { const bool d = ((lane & 2) == 0);  xstep(1, d); intra(d); }          // k=8
    { const bool d = ((lane & 4) == 0);  xstep(2, d); xstep(1, d); intra(d); }            // k=16
    { const bool d = ((lane & 8) == 0);  xstep(4, d); xstep(2, d); xstep(1, d); intra(d); } // k=32
    { const bool d = ((lane & 16) == 0); xstep(8, d); xstep(4, d); xstep(2, d); xstep(1, d); intra(d); } // k=64

    {   // compact: top-64 = elementwise max(i, i+64); valid in lanes 0-15
        u64 o0 = __shfl_xor_sync(0xFFFFFFFFu, a0, 16);
        u64 o1 = __shfl_xor_sync(0xFFFFFFFFu, a1, 16);
        u64 o2 = __shfl_xor_sync(0xFFFFFFFFu, a2, 16);
        u64 o3 = __shfl_xor_sync(0xFFFFFFFFu, a3, 16);
        a0 = a0 > o0 ? a0 : o0; a1 = a1 > o1 ? a1 : o1;
        a2 = a2 > o2 ? a2 : o2; a3 = a3 > o3 ? a3 : o3;
    }
    __syncwarp();
    if (lane < 16) {
        ulonglong2 p0; p0.x = a0; p0.y = a1;
        ulonglong2 p1; p1.x = a2; p1.y = a3;
        ((ulonglong2*)seg)[2 * lane]     = p0;
        ((ulonglong2*)seg)[2 * lane + 1] = p1;
    }
    __syncwarp();
    u64 w0, w1;
    {
        ulonglong2 p = ((const ulonglong2*)seg)[lane];   // positions 2l, 2l+1
        w0 = p.x; w1 = p.y;
    }
    auto mstep2 = [&](u64& x0, u64& x1, int lmask) {
        const bool keepmax = ((lane & lmask) == 0);
        u64 o0 = __shfl_xor_sync(0xFFFFFFFFu, x0, lmask);
        u64 o1 = __shfl_xor_sync(0xFFFFFFFFu, x1, lmask);
        if (keepmax) { x0 = x0 > o0 ? x0 : o0; x1 = x1 > o1 ? x1 : o1; }
        else         { x0 = x0 < o0 ? x0 : o0; x1 = x1 < o1 ? x1 : o1; }
    };
    mstep2(w0, w1, 16); mstep2(w0, w1, 8); mstep2(w0, w1, 4);
    mstep2(w0, w1, 2);  mstep2(w0, w1, 1);
    ce(w0, w1, true);
    {
        ulonglong2 p; p.x = w0; p.y = w1;
        ((ulonglong2*)seg)[lane] = p;                    // seg[0..63] sorted desc
    }
    __syncthreads();
    // keys + w*128 holds warp w's sorted top-64 (desc).

    // --- warp-register merge of two desc-sorted 64-lists -> desc 64 (2/lane) ---
    auto wmerge2 = [&](const u64* La, const u64* Lb, u64& x0, u64& x1) {
        ulonglong2 pa = *(const ulonglong2*)(La + 2 * lane);
        ulonglong2 pb = *(const ulonglong2*)(Lb + 62 - 2 * lane); // reversed pair
        x0 = pa.x > pb.y ? pa.x : pb.y;     // max(A[p], B[63-p]) — bitonic separation
        x1 = pa.y > pb.x ? pa.y : pb.x;
        mstep2(x0, x1, 16); mstep2(x0, x1, 8); mstep2(x0, x1, 4);
        mstep2(x0, x1, 2);  mstep2(x0, x1, 1);
        ce(x0, x1, true);
    };

    // --- CTA merge tree: 8 lists -> 4 -> 2 -> 1 (3 barriers) ---
    u64* mk = (u64*)tiles;
    {
        u64 x0, x1;
        if (warp < 4) {
            wmerge2(keys + (2 * warp) * WR, keys + (2 * warp + 1) * WR, x0, x1);
            ulonglong2 p; p.x = x0; p.y = x1;
            *(ulonglong2*)(mk + warp * 64 + 2 * lane) = p;
        }
        __syncthreads();
        if (warp < 2) {
            wmerge2(mk + (2 * warp) * 64, mk + (2 * warp + 1) * 64, x0, x1);
            ulonglong2 p; p.x = x0; p.y = x1;
            *(ulonglong2*)(mk + (4 + warp) * 64 + 2 * lane) = p;
        }
        __syncthreads();
        if (warp == 0) {
            wmerge2(mk + 4 * 64, mk + 5 * 64, x0, x1);
            ulonglong2 p; p.x = x0; p.y = x1;
            *(ulonglong2*)(g_part + (size_t)blockIdx.x * KK + 2 * lane) = p;
            __threadfence();                             // release (all lanes)
        }
    }
    __syncthreads();

    // --- fused batch merge: last-arriving chunk-CTA finishes the batch ---
    if (tid == 0)
        s_last = (atomicAdd(&g_count[b], 1) == NCHUNK - 1);
    __syncthreads();
    if (!s_last) return;
    __threadfence();                                     // acquire (all threads)

    {
        u64 x0, x1;
        if (warp < 2) {
            const u64* gp = g_part + ((size_t)b * NCHUNK + 2 * warp) * KK;
            wmerge2(gp, gp + KK, x0, x1);
            ulonglong2 p; p.x = x0; p.y = x1;
            *(ulonglong2*)(mk + warp * 64 + 2 * lane) = p;
        }
        __syncthreads();
        if (warp == 0) {
            wmerge2(mk, mk + 64, x0, x1);
            ulonglong2 p; p.x = x0; p.y = x1;
            *(ulonglong2*)(keys + 2 * lane) = p;         // keys[0..63] final desc
        }
    }
    __syncthreads();
    // keys[0..63] = exact global top-64, descending, jax tie-break.

    const u64* sk = keys;
    const float4* seqb4 = (const float4*)(seq + (size_t)b * LL * DD);
    float4* out4 = (float4*)(out_emb + (size_t)b * KK * DD);
#pragma unroll
    for (int u = 0; u < KK * DD / 4 / NTHREADS; u++) {
        const int i   = tid + u * NTHREADS;
        const int kk  = i >> 4;
        const int off = i & 15;
        const int idx = (int)(0xFFFFFFFFu ^ (unsigned int)sk[kk]);
        out4[i] = seqb4[(size_t)idx * (DD / 4) + off];
    }

    if (write_mask && tid < KK) {
        unsigned int fu = (unsigned int)(sk[tid] >> 32);
        unsigned int bits = (fu & 0x80000000u) ? (fu ^ 0x80000000u) : ~fu;
        float s = __uint_as_float(bits);
        out_mask[(size_t)b * KK + tid] = (s > -1e8f) ? 1.0f : 0.0f;
    }

    if (tid == 0) g_count[b] = 0;   // self-reset for next (graph-replayed) launch
}

// ---------------------------------------------------------------------------
extern "C" void kernel_launch(void* const* d_in, const int* in_sizes, int n_in,
                              void* d_out, int out_size)
{
    const float* tgt  = (const float*)d_in[0];
    const float* seq  = (const float*)d_in[2];
    const void*  mask = d_in[4];

    int w_idx = n_in - 1;
    for (int i = n_in - 1; i >= 0; i--) {
        if (in_sizes[i] == DD * DD) { w_idx = i; break; }
    }
    const float* W = (const float*)d_in[w_idx];

    float* out      = (float*)d_out;
    int write_mask  = (out_size >= BB * KK * DD + BB * KK) ? 1 : 0;
    float* out_mask = out + (size_t)BB * KK * DD;

    detect_mask_kernel<<<1, 1024>>>((const unsigned int*)mask);
    gsu_score_kernel<<<BB * NCHUNK, NTHREADS>>>(tgt, seq, mask, W, out, out_mask, write_mask);
}